// round 17
// baseline (speedup 1.0000x reference)
#include <cuda_runtime.h>
#include <cuda_fp16.h>
#include <cstdint>

#define N_NODES   20000
#define M_PAD     20096      // 314 * 64
#define IN_DIM    256
#define OUT_DIM   256
#define FOLD_DIM  128        // 32 q-groups * 4 bases
#define K_DIM     1024       // 8 relations * 128

// Scratch (static device globals — no allocation allowed)
__device__ __half g_hf[N_NODES * FOLD_DIM];        // folded h  [N, 128] fp16
__device__ __half g_U [(size_t)M_PAD * K_DIM];     // aggregated [M_PAD, 1024] fp16
__device__ __half g_Bt[(size_t)OUT_DIM * K_DIM];   // basis^T, K-major, fp16

// ---------------------------------------------------------------------------
// Kernel 1: fold h with w_comp.  hf[n, q*4+b] = sum_p h[n, q*8+p] * w_comp[p,b]
// ---------------------------------------------------------------------------
__global__ void fold_kernel(const float* __restrict__ h,
                            const float* __restrict__ w_comp, int N) {
    __shared__ float wc[32];
    if (threadIdx.x < 32) wc[threadIdx.x] = w_comp[threadIdx.x];
    __syncthreads();

    int idx = blockIdx.x * blockDim.x + threadIdx.x;   // over N*16 (n, q-pair)
    if (idx >= N * 16) return;
    int n  = idx >> 4;
    int q2 = idx & 15;

    const float4* hp = reinterpret_cast<const float4*>(
        h + (size_t)n * IN_DIM + q2 * 16);
    float4 hv4[4];
    hv4[0] = hp[0]; hv4[1] = hp[1]; hv4[2] = hp[2]; hv4[3] = hp[3];
    const float* hv = reinterpret_cast<const float*>(hv4);

    __half2 o[4];
    #pragma unroll
    for (int g = 0; g < 2; g++) {
        float r[4];
        #pragma unroll
        for (int b = 0; b < 4; b++) {
            float s = 0.f;
            #pragma unroll
            for (int p = 0; p < 8; p++) s += hv[g * 8 + p] * wc[p * 4 + b];
            r[b] = s;
        }
        o[g * 2 + 0] = __floats2half2_rn(r[0], r[1]);
        o[g * 2 + 1] = __floats2half2_rn(r[2], r[3]);
    }
    *reinterpret_cast<uint4*>(g_hf + (size_t)n * FOLD_DIM + q2 * 8) =
        *reinterpret_cast<const uint4*>(o);
}

// ---------------------------------------------------------------------------
// Kernel 2: transpose basis [1024,256] -> g_Bt [256,1024] (K-major) as fp16.
// ---------------------------------------------------------------------------
__global__ void transpose_kernel(const float* __restrict__ basis) {
    __shared__ float t[32][33];
    int bx = blockIdx.x;
    int by = blockIdx.y;
    int x = threadIdx.x;
    int y = threadIdx.y;
    #pragma unroll
    for (int i = 0; i < 4; i++)
        t[y + i * 8][x] = basis[(size_t)(bx * 32 + y + i * 8) * OUT_DIM + by * 32 + x];
    __syncthreads();
    #pragma unroll
    for (int i = 0; i < 4; i++)
        g_Bt[(size_t)(by * 32 + y + i * 8) * K_DIM + bx * 32 + x] =
            __float2half_rn(t[x][y + i * 8]);
}

// ---------------------------------------------------------------------------
// Kernel 3: edge scatter, fp16. 16 contiguous lanes per edge, two edges per
// thread (2x MLP), red.add.noftz.v4.f16x2.
// ---------------------------------------------------------------------------
__global__ void scatter_kernel(const int* __restrict__ src,
                               const int* __restrict__ dst,
                               const int* __restrict__ etype, int E) {
    int warp = (blockIdx.x * blockDim.x + threadIdx.x) >> 5;
    int lane = threadIdx.x & 31;
    int e0 = warp * 4 + (lane >> 4);     // edges e0 and e0+2 for this thread
    int e1 = e0 + 2;
    int l = lane & 15;
    if (e0 >= E) return;

    int s0 = __ldg(src + e0);
    int d0 = __ldg(dst + e0);
    int r0 = __ldg(etype + e0);

    bool has1 = (e1 < E);
    int s1 = 0, d1 = 0, r1 = 0;
    if (has1) {
        s1 = __ldg(src + e1);
        d1 = __ldg(dst + e1);
        r1 = __ldg(etype + e1);
    }

    uint4 v0 = *reinterpret_cast<const uint4*>(g_hf + (size_t)s0 * FOLD_DIM + l * 8);
    uint4 v1 = has1
        ? *reinterpret_cast<const uint4*>(g_hf + (size_t)s1 * FOLD_DIM + l * 8)
        : make_uint4(0, 0, 0, 0);

    __half* up0 = g_U + (size_t)d0 * K_DIM + r0 * FOLD_DIM + l * 8;
    asm volatile("red.global.add.noftz.v4.f16x2 [%0], {%1, %2, %3, %4};"
                 :: "l"(up0), "r"(v0.x), "r"(v0.y), "r"(v0.z), "r"(v0.w)
                 : "memory");
    if (has1) {
        __half* up1 = g_U + (size_t)d1 * K_DIM + r1 * FOLD_DIM + l * 8;
        asm volatile("red.global.add.noftz.v4.f16x2 [%0], {%1, %2, %3, %4};"
                     :: "l"(up1), "r"(v1.x), "r"(v1.y), "r"(v1.z), "r"(v1.w)
                     : "memory");
    }
}

// ---------------------------------------------------------------------------
// Kernel 4: fp16 tensor-core GEMM + bias + relu.
// out[M,256] = relu(U[M,1024] @ Bt^T + bias)
// CTA 64(M) x 128(N), 256 threads, 8 warps in 2x4 grid, warp tile 32x32.
// 3 CTAs/SM (24 warps). BK=64, 3-stage cp.async with wait_group(1),
// fully unrolled k-loop, all addresses precomputed/literal.
// ---------------------------------------------------------------------------
#define GBM 64
#define GBN 128
#define GBK 64
#define A_STAGE 8192                       // 64 rows * 128 B
#define B_STAGE 16384                      // 128 rows * 128 B
#define STAGES 3
#define GEMM_SMEM_BYTES (STAGES * (A_STAGE + B_STAGE))   // 73728 B

__device__ __forceinline__ uint32_t smem_u32(const void* p) {
    return (uint32_t)__cvta_generic_to_shared(p);
}

__global__ __launch_bounds__(256, 3)
void gemm_tc_kernel(const __half* __restrict__ Bt,
                    const float* __restrict__ bias,
                    float* __restrict__ out, int M) {
    extern __shared__ char smem[];
    char* As = smem;                           // stages at s*8192
    char* Bs = smem + STAGES * A_STAGE;        // stages at s*16384

    int tid  = threadIdx.x;
    int lane = tid & 31;
    int warp = tid >> 5;
    int wm = warp & 1;                      // rows wm*32
    int wn = warp >> 1;                     // cols wn*32 (0..3)
    int bm = blockIdx.y * GBM;
    int bn = blockIdx.x * GBN;

    float acc[2][4][4];                     // [mf][nf][4]
    #pragma unroll
    for (int mf = 0; mf < 2; mf++)
        #pragma unroll
        for (int nf = 0; nf < 4; nf++)
            #pragma unroll
            for (int i = 0; i < 4; i++) acc[mf][nf][i] = 0.f;

    // ---- staging bases ----
    int r0  = tid >> 3;                    // 0..31
    int seg = tid & 7;
    uint32_t c_st = (uint32_t)(r0 & 7) << 4;
    uint32_t daA = smem_u32(As) + r0 * 128 + ((uint32_t)(seg * 16) ^ c_st);
    uint32_t daB = smem_u32(Bs) + r0 * 128 + ((uint32_t)(seg * 16) ^ c_st);
    const __half* gA = g_U + (size_t)(bm + r0) * K_DIM + seg * 8;
    const __half* gB = Bt + (size_t)(bn + r0) * K_DIM + seg * 8;

    // A: 512 segs/stage -> 2 per thread (rows r0, r0+32)
    // B: 1024 segs/stage -> 4 per thread (rows r0 .. r0+96)
    #define ISSUE_STAGE(S, KOFF)                                                \
        do {                                                                    \
            _Pragma("unroll")                                                   \
            for (int i = 0; i < 2; i++)                                         \
                asm volatile("cp.async.cg.shared.global [%0], [%1], 16;"        \
                             :: "r"(daA + (S) * A_STAGE + i * 4096),            \
                                "l"(gA + (KOFF) + i * 32 * K_DIM) : "memory");  \
            _Pragma("unroll")                                                   \
            for (int i = 0; i < 4; i++)                                         \
                asm volatile("cp.async.cg.shared.global [%0], [%1], 16;"        \
                             :: "r"(daB + (S) * B_STAGE + i * 4096),            \
                                "l"(gB + (KOFF) + i * 32 * K_DIM) : "memory");  \
            asm volatile("cp.async.commit_group;" ::: "memory");                \
        } while (0)

    // ---- fragment LDSM addresses, stage 0 (loop-invariant) ----
    int frow = lane & 15;
    int fkb  = (lane >> 4) * 16;
    uint32_t aaddr[2][4], baddr[2][4];
    {
        uint32_t abase = smem_u32(As);
        uint32_t bbase = smem_u32(Bs);
        #pragma unroll
        for (int mf = 0; mf < 2; mf++) {
            int row = wm * 32 + mf * 16 + frow;
            uint32_t c = (uint32_t)(row & 7) << 4;
            #pragma unroll
            for (int ks = 0; ks < 4; ks++)
                aaddr[mf][ks] = abase + row * 128 + ((uint32_t)(ks * 32 + fkb) ^ c);
        }
        #pragma unroll
        for (int p = 0; p < 2; p++) {
            int row = wn * 32 + p * 16 + frow;
            uint32_t c = (uint32_t)(row & 7) << 4;
            #pragma unroll
            for (int ks = 0; ks < 4; ks++)
                baddr[p][ks] = bbase + row * 128 + ((uint32_t)(ks * 32 + fkb) ^ c);
        }
    }

    #define COMPUTE(S)                                                              \
        do {                                                                        \
            _Pragma("unroll")                                                       \
            for (int ks = 0; ks < 4; ks++) {                                        \
                uint32_t afr[2][4];                                                 \
                _Pragma("unroll")                                                   \
                for (int mf = 0; mf < 2; mf++)                                      \
                    asm volatile(                                                   \
                        "ldmatrix.sync.aligned.m8n8.x4.shared.b16 {%0,%1,%2,%3}, [%4];" \
                        : "=r"(afr[mf][0]), "=r"(afr[mf][1]),                       \
                          "=r"(afr[mf][2]), "=r"(afr[mf][3])                        \
                        : "r"(aaddr[mf][ks] + (S) * A_STAGE));                      \
                uint32_t bfr[4][2];                                                 \
                _Pragma("unroll")                                                   \
                for (int p = 0; p < 2; p++) {                                       \
                    uint32_t r0_, r1_, r2_, r3_;                                    \
                    asm volatile(                                                   \
                        "ldmatrix.sync.aligned.m8n8.x4.shared.b16 {%0,%1,%2,%3}, [%4];" \
                        : "=r"(r0_), "=r"(r1_), "=r"(r2_), "=r"(r3_)                \
                        : "r"(baddr[p][ks] + (S) * B_STAGE));                       \
                    bfr[2 * p][0] = r0_; bfr[2 * p + 1][0] = r1_;                   \
                    bfr[2 * p][1] = r2_; bfr[2 * p + 1][1] = r3_;                   \
                }                                                                   \
                _Pragma("unroll")                                                   \
                for (int mf = 0; mf < 2; mf++)                                      \
                    _Pragma("unroll")                                               \
                    for (int nf = 0; nf < 4; nf++)                                  \
                        asm volatile(                                               \
                            "mma.sync.aligned.m16n8k16.row.col.f32.f16.f16.f32 "    \
                            "{%0,%1,%2,%3}, {%4,%5,%6,%7}, {%8,%9}, {%0,%1,%2,%3};" \
                            : "+f"(acc[mf][nf][0]), "+f"(acc[mf][nf][1]),           \
                              "+f"(acc[mf][nf][2]), "+f"(acc[mf][nf][3])            \
                            : "r"(afr[mf][0]), "r"(afr[mf][1]),                     \
                              "r"(afr[mf][2]), "r"(afr[mf][3]),                     \
                              "r"(bfr[nf][0]), "r"(bfr[nf][1]));                    \
            }                                                                       \
        } while (0)

    // prologue: stages 0,1 <- chunks 0,1
    ISSUE_STAGE(0, 0);
    ISSUE_STAGE(1, 64);

    // fully unrolled: 16 chunks; stage = it%3, wait_group(1) keeps one chunk
    // in flight; final iteration drains with wait_group(0).
    #pragma unroll
    for (int it = 0; it < 16; ++it) {
        if (it < 15)
            asm volatile("cp.async.wait_group 1;" ::: "memory");
        else
            asm volatile("cp.async.wait_group 0;" ::: "memory");
        __syncthreads();

        if (it + 2 < 16)
            ISSUE_STAGE((it + 2) % 3, (it + 2) * 64);

        COMPUTE(it % 3);
    }

    // epilogue: + bias, relu
    #pragma unroll
    for (int mf = 0; mf < 2; mf++) {
        int row0 = bm + wm * 32 + mf * 16 + (lane >> 2);
        #pragma unroll
        for (int nf = 0; nf < 4; nf++) {
            int col = bn + wn * 32 + nf * 8 + (lane & 3) * 2;
            float b0 = __ldg(bias + col);
            float b1 = __ldg(bias + col + 1);
            if (row0 < M) {
                float2 o;
                o.x = fmaxf(acc[mf][nf][0] + b0, 0.f);
                o.y = fmaxf(acc[mf][nf][1] + b1, 0.f);
                *reinterpret_cast<float2*>(out + (size_t)row0 * OUT_DIM + col) = o;
            }
            if (row0 + 8 < M) {
                float2 o;
                o.x = fmaxf(acc[mf][nf][2] + b0, 0.f);
                o.y = fmaxf(acc[mf][nf][3] + b1, 0.f);
                *reinterpret_cast<float2*>(out + (size_t)(row0 + 8) * OUT_DIM + col) = o;
            }
        }
    }
}

// ---------------------------------------------------------------------------
extern "C" void kernel_launch(void* const* d_in, const int* in_sizes, int n_in,
                              void* d_out, int out_size) {
    const float* h      = (const float*)d_in[0];
    const float* basis  = (const float*)d_in[1];
    const float* w_comp = (const float*)d_in[2];
    const float* bias   = (const float*)d_in[3];
    const int*   src    = (const int*)d_in[4];
    const int*   dst    = (const int*)d_in[5];
    const int*   etype  = (const int*)d_in[6];
    float* out = (float*)d_out;

    int N = in_sizes[0] / IN_DIM;   // 20000
    int E = in_sizes[4];            // 320000

    static cudaStream_t s1 = nullptr, s2 = nullptr;
    static cudaEvent_t e0 = nullptr, e1 = nullptr, e2 = nullptr;
    static bool init_done = false;
    if (!init_done) {
        cudaFuncSetAttribute(gemm_tc_kernel,
                             cudaFuncAttributeMaxDynamicSharedMemorySize,
                             GEMM_SMEM_BYTES);
        cudaStreamCreateWithFlags(&s1, cudaStreamNonBlocking);
        cudaStreamCreateWithFlags(&s2, cudaStreamNonBlocking);
        cudaEventCreateWithFlags(&e0, cudaEventDisableTiming);
        cudaEventCreateWithFlags(&e1, cudaEventDisableTiming);
        cudaEventCreateWithFlags(&e2, cudaEventDisableTiming);
        init_done = true;
    }

    void* uptr = nullptr;
    cudaGetSymbolAddress(&uptr, g_U);
    __half* btp = nullptr;
    cudaGetSymbolAddress((void**)&btp, g_Bt);

    // fork: memset U on s1; transpose on s2 (joined only before GEMM)
    cudaEventRecord(e0, 0);
    cudaStreamWaitEvent(s1, e0, 0);
    cudaStreamWaitEvent(s2, e0, 0);

    cudaMemsetAsync(uptr, 0, (size_t)M_PAD * K_DIM * sizeof(__half), s1);  // #1
    cudaEventRecord(e1, s1);

    fold_kernel<<<(N * 16 + 255) / 256, 256>>>(h, w_comp, N);              // #2

    transpose_kernel<<<dim3(32, 8), dim3(32, 8), 0, s2>>>(basis);          // #3
    cudaEventRecord(e2, s2);

    cudaStreamWaitEvent(0, e1, 0);   // scatter needs zeroed U (+ fold on main)

    scatter_kernel<<<(E + 31) / 32, 256>>>(src, dst, etype, E);            // #4

    cudaStreamWaitEvent(0, e2, 0);   // GEMM needs Bt

    dim3 grid(OUT_DIM / GBN, M_PAD / GBM);   // (2, 314)
    gemm_tc_kernel<<<grid, 256, GEMM_SMEM_BYTES>>>(btp, bias, out, N);     // #5 (ncu)
}